// round 10
// baseline (speedup 1.0000x reference)
#include <cuda_runtime.h>
#include <cuda_bf16.h>
#include <cuda_fp8.h>
#include <math.h>
#include <stdint.h>

#define NROWS 8192
#define DDIM  256
#define TWO_N 16384
// fp8 tiles: A(32KB) + B0(32KB) + B1(32KB)
#define TILE_BYTES 32768
#define SMEM_BYTES (3 * TILE_BYTES)

// scratch: normalized z rows quantized to e4m3, [z1hat; z2hat] = [16384, 256] bytes/row
__device__ uint8_t g_Zn8[(size_t)TWO_N * DDIM];
// per-row sum of exp(sim-10), masked diag
__device__ float g_rsum[TWO_N];
// accumulators: 0=price 1=change 2=crit 3=posdot 4=lse_sum
__device__ float g_acc[8];

// ---------------------------------------------------------------------------
__global__ void init_kernel() {
    int i = blockIdx.x * blockDim.x + threadIdx.x;
    if (i < TWO_N) g_rsum[i] = 0.f;
    if (i < 8) g_acc[i] = 0.f;
}

// ---------------------------------------------------------------------------
__device__ __forceinline__ uint32_t pack4_e4m3(float x, float y, float z, float w) {
    __nv_fp8x2_storage_t lo =
        __nv_cvt_float2_to_fp8x2(make_float2(x, y), __NV_SATFINITE, __NV_E4M3);
    __nv_fp8x2_storage_t hi =
        __nv_cvt_float2_to_fp8x2(make_float2(z, w), __NV_SATFINITE, __NV_E4M3);
    return (uint32_t)lo | ((uint32_t)hi << 16);
}

// Normalize z1/z2 rows (fp32), write e4m3 rows to g_Zn8, accumulate positive-pair dots.
__global__ void prep_kernel(const float* __restrict__ z1, const float* __restrict__ z2) {
    int warp = (blockIdx.x * blockDim.x + threadIdx.x) >> 5;
    int lane = threadIdx.x & 31;
    if (warp >= NROWS) return;

    const float4* r1 = (const float4*)(z1 + (size_t)warp * DDIM);
    const float4* r2 = (const float4*)(z2 + (size_t)warp * DDIM);
    float4 a0 = r1[lane * 2], a1 = r1[lane * 2 + 1];
    float4 b0 = r2[lane * 2], b1 = r2[lane * 2 + 1];

    float s11 = a0.x*a0.x + a0.y*a0.y + a0.z*a0.z + a0.w*a0.w
              + a1.x*a1.x + a1.y*a1.y + a1.z*a1.z + a1.w*a1.w;
    float s22 = b0.x*b0.x + b0.y*b0.y + b0.z*b0.z + b0.w*b0.w
              + b1.x*b1.x + b1.y*b1.y + b1.z*b1.z + b1.w*b1.w;
    float s12 = a0.x*b0.x + a0.y*b0.y + a0.z*b0.z + a0.w*b0.w
              + a1.x*b1.x + a1.y*b1.y + a1.z*b1.z + a1.w*b1.w;
    #pragma unroll
    for (int o = 16; o; o >>= 1) {
        s11 += __shfl_xor_sync(0xffffffffu, s11, o);
        s22 += __shfl_xor_sync(0xffffffffu, s22, o);
        s12 += __shfl_xor_sync(0xffffffffu, s12, o);
    }
    float n1 = fmaxf(sqrtf(s11), 1e-12f);
    float n2 = fmaxf(sqrtf(s22), 1e-12f);
    float i1 = 1.f / n1, i2 = 1.f / n2;

    // 8 bytes per lane per row
    uint2 u1, u2;
    u1.x = pack4_e4m3(a0.x * i1, a0.y * i1, a0.z * i1, a0.w * i1);
    u1.y = pack4_e4m3(a1.x * i1, a1.y * i1, a1.z * i1, a1.w * i1);
    u2.x = pack4_e4m3(b0.x * i2, b0.y * i2, b0.z * i2, b0.w * i2);
    u2.y = pack4_e4m3(b1.x * i2, b1.y * i2, b1.z * i2, b1.w * i2);
    ((uint2*)(g_Zn8 + (size_t)warp * DDIM))[lane] = u1;
    ((uint2*)(g_Zn8 + (size_t)(warp + NROWS) * DDIM))[lane] = u2;

    if (lane == 0) atomicAdd(&g_acc[3], s12 * i1 * i2);
}

// ---------------------------------------------------------------------------
// Supervised scalar losses: MSE(price) + MSE(change) + BCEWithLogits(crit)
__global__ void sup_kernel(const float* __restrict__ pp, const float* __restrict__ pt,
                           const float* __restrict__ cp, const float* __restrict__ ct,
                           const float* __restrict__ xp, const float* __restrict__ xt) {
    float s0 = 0.f, s1 = 0.f, s2 = 0.f;
    for (int i = blockIdx.x * blockDim.x + threadIdx.x; i < NROWS;
         i += gridDim.x * blockDim.x) {
        float d = pp[i] - pt[i]; s0 = fmaf(d, d, s0);
        d = cp[i] - ct[i];       s1 = fmaf(d, d, s1);
        float x = xp[i], t = xt[i];
        s2 += fmaxf(x, 0.f) - x * t + log1pf(expf(-fabsf(x)));
    }
    #pragma unroll
    for (int o = 16; o; o >>= 1) {
        s0 += __shfl_xor_sync(0xffffffffu, s0, o);
        s1 += __shfl_xor_sync(0xffffffffu, s1, o);
        s2 += __shfl_xor_sync(0xffffffffu, s2, o);
    }
    __shared__ float sh[3][8];
    int lane = threadIdx.x & 31, w = threadIdx.x >> 5;
    if (lane == 0) { sh[0][w] = s0; sh[1][w] = s1; sh[2][w] = s2; }
    __syncthreads();
    if (threadIdx.x == 0) {
        float t0 = 0.f, t1 = 0.f, t2 = 0.f;
        for (int k = 0; k < 8; k++) { t0 += sh[0][k]; t1 += sh[1][k]; t2 += sh[2][k]; }
        atomicAdd(&g_acc[0], t0);
        atomicAdd(&g_acc[1], t1);
        atomicAdd(&g_acc[2], t2);
    }
}

// ---------------------------------------------------------------------------
// FP8 GEMM + exp + symmetric row/col accumulation.
// fp8 tile row = 256 bytes = 16 chunks of 16B; swizzle XORs low 3 chunk bits.
__device__ __forceinline__ uint32_t sw_off8(int r, int ch) {
    return (uint32_t)(r * 256 + ((((ch ^ r) & 7) | (ch & 8)) << 4));
}

__device__ __forceinline__ void ldsm4(uint32_t* r, uint32_t addr) {
    asm("ldmatrix.sync.aligned.m8n8.x4.shared.b16 {%0,%1,%2,%3}, [%4];"
        : "=r"(r[0]), "=r"(r[1]), "=r"(r[2]), "=r"(r[3]) : "r"(addr) : "memory");
}

// D(f32) += A(e4m3) * B(e4m3)^T, m16n8k32
__device__ __forceinline__ void mma_fp8(float* c, const uint32_t* a, const uint32_t* b) {
    asm("mma.sync.aligned.m16n8k32.row.col.f32.e4m3.e4m3.f32 "
        "{%0,%1,%2,%3}, {%4,%5,%6,%7}, {%8,%9}, {%0,%1,%2,%3};"
        : "+f"(c[0]), "+f"(c[1]), "+f"(c[2]), "+f"(c[3])
        : "r"(a[0]), "r"(a[1]), "r"(a[2]), "r"(a[3]), "r"(b[0]), "r"(b[1]));
}

__device__ __forceinline__ void cp16(uint32_t dst, const void* src) {
    asm volatile("cp.async.cg.shared.global [%0], [%1], 16;"
                 :: "r"(dst), "l"(src));
}
__device__ __forceinline__ void cp_commit() {
    asm volatile("cp.async.commit_group;");
}
template <int N>
__device__ __forceinline__ void cp_wait() {
    asm volatile("cp.async.wait_group %0;" :: "n"(N) : "memory");
}

// exp(10*v - 10) = exp2(v*K - K), K = 10*log2(e); single MUFU EX2
__device__ __forceinline__ float ex2(float x) {
    float r;
    asm("ex2.approx.f32 %0, %1;" : "=f"(r) : "f"(x));
    return r;
}
#define EXPK 14.4269504088896f

__global__ void __launch_bounds__(256, 1) ntxent_kernel() {
    extern __shared__ char smem[];
    const int tid  = threadIdx.x;
    const int lane = tid & 31;
    const int wid  = tid >> 5;
    const int warpM = wid >> 1;  // 0..3 (rows)
    const int warpN = wid & 1;   // 0..1 (cols)
    const int br = blockIdx.x;   // 0..127 row block
    // wrap mapping: CTA br computes tiles j = br..br+63 (mod 128),
    // plus antipodal j=br+64 when br<64. Each unordered pair once.
    const int ntiles = (br < 64) ? 65 : 64;

    const uint4* gz = (const uint4*)g_Zn8;  // 16 uint4 per 256-byte row

    uint32_t sbase = (uint32_t)__cvta_generic_to_shared(smem);
    const uint32_t sA = sbase;
    const uint32_t sB[2] = {sbase + TILE_BYTES, sbase + 2 * TILE_BYTES};

    // prologue: A tile (rows br*128..) + B tile jj=0 (j=br, the diag tile)
    // 128 rows x 16 chunks = 2048 chunks / 256 threads = 8 per thread
    #pragma unroll
    for (int it = 0; it < 8; it++) {
        int idx = tid + it * 256;
        int r = idx >> 4, ch = idx & 15;
        uint32_t off = sw_off8(r, ch);
        cp16(sA + off, gz + (size_t)(br * 128 + r) * 16 + ch);
        cp16(sB[0] + off, gz + (size_t)(br * 128 + r) * 16 + ch);
    }
    cp_commit();

    const int g = lane >> 2, q = lane & 3;
    float racc[4] = {0.f, 0.f, 0.f, 0.f};

    const int ar_base = warpM * 32 + (lane & 15);
    const int a_chadd = lane >> 4;          // k-chunk half (16B)
    const int bn_thr  = warpN * 64 + ((lane >> 4) << 3) + (lane & 7);
    const int b_chadd = (lane >> 3) & 1;

    for (int jj = 0; jj < ntiles; jj++) {
        const int j = (br + jj) & 127;
        const int cur = jj & 1;
        if (jj + 1 < ntiles) {
            const int nxt = cur ^ 1;
            const int j2 = (br + jj + 1) & 127;
            #pragma unroll
            for (int it = 0; it < 8; it++) {
                int idx = tid + it * 256;
                int r = idx >> 4, ch = idx & 15;
                cp16(sB[nxt] + sw_off8(r, ch),
                     gz + (size_t)(j2 * 128 + r) * 16 + ch);
            }
            cp_commit();
            cp_wait<1>();   // current tile's group has landed
        } else {
            cp_wait<0>();
        }
        __syncthreads();

        float c[2][8][4];
        #pragma unroll
        for (int mt = 0; mt < 2; mt++)
            #pragma unroll
            for (int nt = 0; nt < 8; nt++)
                #pragma unroll
                for (int e = 0; e < 4; e++) c[mt][nt][e] = 0.f;

        #pragma unroll
        for (int ks = 0; ks < 8; ks++) {   // K=256 bytes / 32 per mma
            uint32_t a[2][4];
            #pragma unroll
            for (int mt = 0; mt < 2; mt++) {
                int r  = ar_base + mt * 16;
                int ch = ks * 2 + a_chadd;
                ldsm4(a[mt], sA + sw_off8(r, ch));
            }
            uint32_t b[8][2];
            #pragma unroll
            for (int p = 0; p < 4; p++) {
                int n  = bn_thr + p * 16;
                int ch = ks * 2 + b_chadd;
                uint32_t t[4];
                ldsm4(t, sB[cur] + sw_off8(n, ch));
                b[2 * p][0] = t[0]; b[2 * p][1] = t[1];
                b[2 * p + 1][0] = t[2]; b[2 * p + 1][1] = t[3];
            }
            #pragma unroll
            for (int mt = 0; mt < 2; mt++)
                #pragma unroll
                for (int nt = 0; nt < 8; nt++)
                    mma_fp8(c[mt][nt], a[mt], b[nt]);
        }

        // epilogue: exp(10*sim - 10); row-side into racc, col-side (transpose,
        // feeds row sums of block j) via shfl-reduce + global float atomics.
        const bool diag = (jj == 0);
        #pragma unroll
        for (int nt = 0; nt < 8; nt++) {
            float cs0 = 0.f, cs1 = 0.f;
            #pragma unroll
            for (int mt = 0; mt < 2; mt++) {
                #pragma unroll
                for (int h = 0; h < 2; h++) {
                    float e0 = ex2(fmaf(c[mt][nt][h * 2 + 0], EXPK, -EXPK));
                    float e1 = ex2(fmaf(c[mt][nt][h * 2 + 1], EXPK, -EXPK));
                    if (diag) {
                        int rl = warpM * 32 + mt * 16 + h * 8 + g;
                        int cb = warpN * 64 + nt * 8 + 2 * q;
                        if (rl == cb)     e0 = 0.f;
                        if (rl == cb + 1) e1 = 0.f;
                    }
                    racc[mt * 2 + h] += e0 + e1;
                    cs0 += e0; cs1 += e1;
                }
            }
            if (!diag) {
                #pragma unroll
                for (int o = 4; o <= 16; o <<= 1) {
                    cs0 += __shfl_xor_sync(0xffffffffu, cs0, o);
                    cs1 += __shfl_xor_sync(0xffffffffu, cs1, o);
                }
                if (lane < 4) {
                    int col = warpN * 64 + nt * 8 + 2 * lane;
                    atomicAdd(&g_rsum[j * 128 + col],     cs0);
                    atomicAdd(&g_rsum[j * 128 + col + 1], cs1);
                }
            }
        }
        __syncthreads();  // all reads of sB[cur] done before it is overwritten
    }

    // row-side: reduce racc across quad lanes, one atomic per row per warp
    #pragma unroll
    for (int k = 0; k < 4; k++) {
        float v = racc[k];
        v += __shfl_xor_sync(0xffffffffu, v, 1);
        v += __shfl_xor_sync(0xffffffffu, v, 2);
        if (q == 0) {
            int r = warpM * 32 + (k >> 1) * 16 + (k & 1) * 8 + g;
            atomicAdd(&g_rsum[br * 128 + r], v);
        }
    }
}

// ---------------------------------------------------------------------------
__global__ void lse_kernel() {
    int i = blockIdx.x * blockDim.x + threadIdx.x;
    float lse = 10.f + __logf(g_rsum[i]);
    #pragma unroll
    for (int o = 16; o; o >>= 1) lse += __shfl_xor_sync(0xffffffffu, lse, o);
    __shared__ float sh[8];
    int lane = threadIdx.x & 31, w = threadIdx.x >> 5;
    if (lane == 0) sh[w] = lse;
    __syncthreads();
    if (threadIdx.x == 0) {
        float t = 0.f;
        for (int k = 0; k < 8; k++) t += sh[k];
        atomicAdd(&g_acc[4], t);
    }
}

// ---------------------------------------------------------------------------
__global__ void finish_kernel(float* out) {
    const float inv = 1.f / 8192.f;
    float sup = g_acc[0] * inv + 0.5f * g_acc[1] * inv + 0.3f * g_acc[2] * inv;
    // sum_i sim_pos = 2 * posdotsum / 0.1 = 20 * posdotsum
    float ssl = (g_acc[4] - 20.f * g_acc[3]) * (1.f / 16384.f);
    out[0] = sup + 0.1f * ssl;
}

// ---------------------------------------------------------------------------
extern "C" void kernel_launch(void* const* d_in, const int* in_sizes, int n_in,
                              void* d_out, int out_size) {
    const float* pp = (const float*)d_in[0];
    const float* pt = (const float*)d_in[1];
    const float* cp = (const float*)d_in[2];
    const float* ct = (const float*)d_in[3];
    const float* xp = (const float*)d_in[4];
    const float* xt = (const float*)d_in[5];
    const float* z1 = (const float*)d_in[6];
    const float* z2 = (const float*)d_in[7];
    float* out = (float*)d_out;

    cudaFuncSetAttribute(ntxent_kernel, cudaFuncAttributeMaxDynamicSharedMemorySize,
                         SMEM_BYTES);

    init_kernel<<<64, 256>>>();
    prep_kernel<<<NROWS / 8, 256>>>(z1, z2);
    sup_kernel<<<32, 256>>>(pp, pt, cp, ct, xp, xt);
    ntxent_kernel<<<128, 256, SMEM_BYTES>>>();
    lse_kernel<<<64, 256>>>();
    finish_kernel<<<1, 1>>>(out);
}

// round 11
// speedup vs baseline: 1.0688x; 1.0688x over previous
#include <cuda_runtime.h>
#include <cuda_bf16.h>
#include <cuda_fp8.h>
#include <math.h>
#include <stdint.h>

#define NROWS 8192
#define DDIM  256
#define TWO_N 16384
// A(32KB) + B0(16KB) + B1(16KB) = 64KB, padded to 96KB => exactly 2 CTAs/SM
#define SMEM_BYTES 98304

// scratch: normalized z rows quantized to e4m3, [z1hat; z2hat] = [16384, 256] bytes/row
__device__ uint8_t g_Zn8[(size_t)TWO_N * DDIM];
// per-row sum of exp(sim-10), masked diag
__device__ float g_rsum[TWO_N];
// accumulators: 0=price 1=change 2=crit 3=posdot 4=lse_sum
__device__ float g_acc[8];

// ---------------------------------------------------------------------------
__global__ void init_kernel() {
    int i = blockIdx.x * blockDim.x + threadIdx.x;
    if (i < TWO_N) g_rsum[i] = 0.f;
    if (i < 8) g_acc[i] = 0.f;
}

// ---------------------------------------------------------------------------
__device__ __forceinline__ uint32_t pack4_e4m3(float x, float y, float z, float w) {
    __nv_fp8x2_storage_t lo =
        __nv_cvt_float2_to_fp8x2(make_float2(x, y), __NV_SATFINITE, __NV_E4M3);
    __nv_fp8x2_storage_t hi =
        __nv_cvt_float2_to_fp8x2(make_float2(z, w), __NV_SATFINITE, __NV_E4M3);
    return (uint32_t)lo | ((uint32_t)hi << 16);
}

// Normalize z1/z2 rows (fp32), write e4m3 rows to g_Zn8, accumulate positive-pair dots.
__global__ void prep_kernel(const float* __restrict__ z1, const float* __restrict__ z2) {
    int warp = (blockIdx.x * blockDim.x + threadIdx.x) >> 5;
    int lane = threadIdx.x & 31;
    if (warp >= NROWS) return;

    const float4* r1 = (const float4*)(z1 + (size_t)warp * DDIM);
    const float4* r2 = (const float4*)(z2 + (size_t)warp * DDIM);
    float4 a0 = r1[lane * 2], a1 = r1[lane * 2 + 1];
    float4 b0 = r2[lane * 2], b1 = r2[lane * 2 + 1];

    float s11 = a0.x*a0.x + a0.y*a0.y + a0.z*a0.z + a0.w*a0.w
              + a1.x*a1.x + a1.y*a1.y + a1.z*a1.z + a1.w*a1.w;
    float s22 = b0.x*b0.x + b0.y*b0.y + b0.z*b0.z + b0.w*b0.w
              + b1.x*b1.x + b1.y*b1.y + b1.z*b1.z + b1.w*b1.w;
    float s12 = a0.x*b0.x + a0.y*b0.y + a0.z*b0.z + a0.w*b0.w
              + a1.x*b1.x + a1.y*b1.y + a1.z*b1.z + a1.w*b1.w;
    #pragma unroll
    for (int o = 16; o; o >>= 1) {
        s11 += __shfl_xor_sync(0xffffffffu, s11, o);
        s22 += __shfl_xor_sync(0xffffffffu, s22, o);
        s12 += __shfl_xor_sync(0xffffffffu, s12, o);
    }
    float n1 = fmaxf(sqrtf(s11), 1e-12f);
    float n2 = fmaxf(sqrtf(s22), 1e-12f);
    float i1 = 1.f / n1, i2 = 1.f / n2;

    uint2 u1, u2;
    u1.x = pack4_e4m3(a0.x * i1, a0.y * i1, a0.z * i1, a0.w * i1);
    u1.y = pack4_e4m3(a1.x * i1, a1.y * i1, a1.z * i1, a1.w * i1);
    u2.x = pack4_e4m3(b0.x * i2, b0.y * i2, b0.z * i2, b0.w * i2);
    u2.y = pack4_e4m3(b1.x * i2, b1.y * i2, b1.z * i2, b1.w * i2);
    ((uint2*)(g_Zn8 + (size_t)warp * DDIM))[lane] = u1;
    ((uint2*)(g_Zn8 + (size_t)(warp + NROWS) * DDIM))[lane] = u2;

    if (lane == 0) atomicAdd(&g_acc[3], s12 * i1 * i2);
}

// ---------------------------------------------------------------------------
// Supervised scalar losses: MSE(price) + MSE(change) + BCEWithLogits(crit)
__global__ void sup_kernel(const float* __restrict__ pp, const float* __restrict__ pt,
                           const float* __restrict__ cp, const float* __restrict__ ct,
                           const float* __restrict__ xp, const float* __restrict__ xt) {
    float s0 = 0.f, s1 = 0.f, s2 = 0.f;
    for (int i = blockIdx.x * blockDim.x + threadIdx.x; i < NROWS;
         i += gridDim.x * blockDim.x) {
        float d = pp[i] - pt[i]; s0 = fmaf(d, d, s0);
        d = cp[i] - ct[i];       s1 = fmaf(d, d, s1);
        float x = xp[i], t = xt[i];
        s2 += fmaxf(x, 0.f) - x * t + log1pf(expf(-fabsf(x)));
    }
    #pragma unroll
    for (int o = 16; o; o >>= 1) {
        s0 += __shfl_xor_sync(0xffffffffu, s0, o);
        s1 += __shfl_xor_sync(0xffffffffu, s1, o);
        s2 += __shfl_xor_sync(0xffffffffu, s2, o);
    }
    __shared__ float sh[3][8];
    int lane = threadIdx.x & 31, w = threadIdx.x >> 5;
    if (lane == 0) { sh[0][w] = s0; sh[1][w] = s1; sh[2][w] = s2; }
    __syncthreads();
    if (threadIdx.x == 0) {
        float t0 = 0.f, t1 = 0.f, t2 = 0.f;
        for (int k = 0; k < 8; k++) { t0 += sh[0][k]; t1 += sh[1][k]; t2 += sh[2][k]; }
        atomicAdd(&g_acc[0], t0);
        atomicAdd(&g_acc[1], t1);
        atomicAdd(&g_acc[2], t2);
    }
}

// ---------------------------------------------------------------------------
// FP8 GEMM + exp + symmetric row/col accumulation.
// fp8 tile row = 256 bytes = 16 chunks of 16B; swizzle XORs low 3 chunk bits.
__device__ __forceinline__ uint32_t sw_off8(int r, int ch) {
    return (uint32_t)(r * 256 + ((((ch ^ r) & 7) | (ch & 8)) << 4));
}

__device__ __forceinline__ void ldsm4(uint32_t* r, uint32_t addr) {
    asm("ldmatrix.sync.aligned.m8n8.x4.shared.b16 {%0,%1,%2,%3}, [%4];"
        : "=r"(r[0]), "=r"(r[1]), "=r"(r[2]), "=r"(r[3]) : "r"(addr) : "memory");
}

// D(f32) += A(e4m3) * B(e4m3)^T, m16n8k32
__device__ __forceinline__ void mma_fp8(float* c, const uint32_t* a, const uint32_t* b) {
    asm("mma.sync.aligned.m16n8k32.row.col.f32.e4m3.e4m3.f32 "
        "{%0,%1,%2,%3}, {%4,%5,%6,%7}, {%8,%9}, {%0,%1,%2,%3};"
        : "+f"(c[0]), "+f"(c[1]), "+f"(c[2]), "+f"(c[3])
        : "r"(a[0]), "r"(a[1]), "r"(a[2]), "r"(a[3]), "r"(b[0]), "r"(b[1]));
}

__device__ __forceinline__ void cp16(uint32_t dst, const void* src) {
    asm volatile("cp.async.cg.shared.global [%0], [%1], 16;"
                 :: "r"(dst), "l"(src));
}
__device__ __forceinline__ void cp_commit() {
    asm volatile("cp.async.commit_group;");
}
template <int N>
__device__ __forceinline__ void cp_wait() {
    asm volatile("cp.async.wait_group %0;" :: "n"(N) : "memory");
}

// exp(10*v - 10) = exp2(v*K - K), K = 10*log2(e); single MUFU EX2
__device__ __forceinline__ float ex2(float x) {
    float r;
    asm("ex2.approx.f32 %0, %1;" : "=f"(r) : "f"(x));
    return r;
}
#define EXPK 14.4269504088896f

// CTA = 128 threads (4 warps), computes 128 rows x 64 cols of each tile in its
// wrap list. Grid 256 = (row-block br, column half). Two CTAs per SM overlap.
__global__ void __launch_bounds__(128, 2) ntxent_kernel() {
    extern __shared__ char smem[];
    const int tid  = threadIdx.x;
    const int lane = tid & 31;
    const int warpM = tid >> 5;        // 0..3 (32 rows each)
    const int br   = blockIdx.x >> 1;  // 0..127 row block
    const int half = blockIdx.x & 1;   // 0..1 column half of B tiles
    // wrap mapping: row-block br pairs with j = br..br+63 (mod 128),
    // plus antipodal j=br+64 when br<64. Each unordered pair once.
    const int ntiles = (br < 64) ? 65 : 64;

    const uint4* gz = (const uint4*)g_Zn8;  // 16 uint4 per 256-byte row

    uint32_t sbase = (uint32_t)__cvta_generic_to_shared(smem);
    const uint32_t sA = sbase;                               // 32KB
    const uint32_t sB[2] = {sbase + 32768, sbase + 49152};   // 16KB each

    // prologue: A tile (rows br*128.., 2048 chunks / 128 thr = 16 each)
    //           B half-tile jj=0 (rows br*128 + half*64.., 1024 chunks = 8 each)
    #pragma unroll
    for (int it = 0; it < 16; it++) {
        int idx = tid + it * 128;
        int r = idx >> 4, ch = idx & 15;
        cp16(sA + sw_off8(r, ch), gz + (size_t)(br * 128 + r) * 16 + ch);
    }
    #pragma unroll
    for (int it = 0; it < 8; it++) {
        int idx = tid + it * 128;
        int r = idx >> 4, ch = idx & 15;
        cp16(sB[0] + sw_off8(r, ch),
             gz + (size_t)(br * 128 + half * 64 + r) * 16 + ch);
    }
    cp_commit();

    const int g = lane >> 2, q = lane & 3;
    float racc[4] = {0.f, 0.f, 0.f, 0.f};

    const int ar_base = warpM * 32 + (lane & 15);
    const int a_chadd = lane >> 4;
    const int bn_thr  = ((lane >> 4) << 3) + (lane & 7);   // local row in 64-row B tile
    const int b_chadd = (lane >> 3) & 1;

    for (int jj = 0; jj < ntiles; jj++) {
        const int j = (br + jj) & 127;
        const int cur = jj & 1;
        if (jj + 1 < ntiles) {
            const int nxt = cur ^ 1;
            const int j2 = (br + jj + 1) & 127;
            #pragma unroll
            for (int it = 0; it < 8; it++) {
                int idx = tid + it * 128;
                int r = idx >> 4, ch = idx & 15;
                cp16(sB[nxt] + sw_off8(r, ch),
                     gz + (size_t)(j2 * 128 + half * 64 + r) * 16 + ch);
            }
            cp_commit();
            cp_wait<1>();   // current tile's group has landed
        } else {
            cp_wait<0>();
        }
        __syncthreads();

        float c[2][8][4];
        #pragma unroll
        for (int mt = 0; mt < 2; mt++)
            #pragma unroll
            for (int nt = 0; nt < 8; nt++)
                #pragma unroll
                for (int e = 0; e < 4; e++) c[mt][nt][e] = 0.f;

        #pragma unroll
        for (int ks = 0; ks < 8; ks++) {   // K=256 bytes / 32 per mma
            uint32_t a[2][4];
            #pragma unroll
            for (int mt = 0; mt < 2; mt++) {
                int r  = ar_base + mt * 16;
                int ch = ks * 2 + a_chadd;
                ldsm4(a[mt], sA + sw_off8(r, ch));
            }
            uint32_t b[8][2];
            #pragma unroll
            for (int p = 0; p < 4; p++) {
                int n  = bn_thr + p * 16;
                int ch = ks * 2 + b_chadd;
                uint32_t t[4];
                ldsm4(t, sB[cur] + sw_off8(n, ch));
                b[2 * p][0] = t[0]; b[2 * p][1] = t[1];
                b[2 * p + 1][0] = t[2]; b[2 * p + 1][1] = t[3];
            }
            #pragma unroll
            for (int mt = 0; mt < 2; mt++)
                #pragma unroll
                for (int nt = 0; nt < 8; nt++)
                    mma_fp8(c[mt][nt], a[mt], b[nt]);
        }

        // epilogue: exp(10*sim - 10); row-side into racc, col-side (transpose,
        // feeds row sums of block j) via shfl-reduce + global float atomics.
        const bool diag = (jj == 0);
        #pragma unroll
        for (int nt = 0; nt < 8; nt++) {
            float cs0 = 0.f, cs1 = 0.f;
            #pragma unroll
            for (int mt = 0; mt < 2; mt++) {
                #pragma unroll
                for (int h = 0; h < 2; h++) {
                    float e0 = ex2(fmaf(c[mt][nt][h * 2 + 0], EXPK, -EXPK));
                    float e1 = ex2(fmaf(c[mt][nt][h * 2 + 1], EXPK, -EXPK));
                    if (diag) {
                        int rl = warpM * 32 + mt * 16 + h * 8 + g;
                        int cb = half * 64 + nt * 8 + 2 * q;
                        if (rl == cb)     e0 = 0.f;
                        if (rl == cb + 1) e1 = 0.f;
                    }
                    racc[mt * 2 + h] += e0 + e1;
                    cs0 += e0; cs1 += e1;
                }
            }
            if (!diag) {
                #pragma unroll
                for (int o = 4; o <= 16; o <<= 1) {
                    cs0 += __shfl_xor_sync(0xffffffffu, cs0, o);
                    cs1 += __shfl_xor_sync(0xffffffffu, cs1, o);
                }
                if (lane < 4) {
                    int col = half * 64 + nt * 8 + 2 * lane;
                    atomicAdd(&g_rsum[j * 128 + col],     cs0);
                    atomicAdd(&g_rsum[j * 128 + col + 1], cs1);
                }
            }
        }
        __syncthreads();  // all reads of sB[cur] done before it is overwritten
    }

    // row-side: reduce racc across quad lanes, one atomic per row per warp
    #pragma unroll
    for (int k = 0; k < 4; k++) {
        float v = racc[k];
        v += __shfl_xor_sync(0xffffffffu, v, 1);
        v += __shfl_xor_sync(0xffffffffu, v, 2);
        if (q == 0) {
            int r = warpM * 32 + (k >> 1) * 16 + (k & 1) * 8 + g;
            atomicAdd(&g_rsum[br * 128 + r], v);
        }
    }
}

// ---------------------------------------------------------------------------
__global__ void lse_kernel() {
    int i = blockIdx.x * blockDim.x + threadIdx.x;
    float lse = 10.f + __logf(g_rsum[i]);
    #pragma unroll
    for (int o = 16; o; o >>= 1) lse += __shfl_xor_sync(0xffffffffu, lse, o);
    __shared__ float sh[8];
    int lane = threadIdx.x & 31, w = threadIdx.x >> 5;
    if (lane == 0) sh[w] = lse;
    __syncthreads();
    if (threadIdx.x == 0) {
        float t = 0.f;
        for (int k = 0; k < 8; k++) t += sh[k];
        atomicAdd(&g_acc[4], t);
    }
}

// ---------------------------------------------------------------------------
__global__ void finish_kernel(float* out) {
    const float inv = 1.f / 8192.f;
    float sup = g_acc[0] * inv + 0.5f * g_acc[1] * inv + 0.3f * g_acc[2] * inv;
    // sum_i sim_pos = 2 * posdotsum / 0.1 = 20 * posdotsum
    float ssl = (g_acc[4] - 20.f * g_acc[3]) * (1.f / 16384.f);
    out[0] = sup + 0.1f * ssl;
}

// ---------------------------------------------------------------------------
extern "C" void kernel_launch(void* const* d_in, const int* in_sizes, int n_in,
                              void* d_out, int out_size) {
    const float* pp = (const float*)d_in[0];
    const float* pt = (const float*)d_in[1];
    const float* cp = (const float*)d_in[2];
    const float* ct = (const float*)d_in[3];
    const float* xp = (const float*)d_in[4];
    const float* xt = (const float*)d_in[5];
    const float* z1 = (const float*)d_in[6];
    const float* z2 = (const float*)d_in[7];
    float* out = (float*)d_out;

    cudaFuncSetAttribute(ntxent_kernel, cudaFuncAttributeMaxDynamicSharedMemorySize,
                         SMEM_BYTES);

    init_kernel<<<64, 256>>>();
    prep_kernel<<<NROWS / 8, 256>>>(z1, z2);
    sup_kernel<<<32, 256>>>(pp, pt, cp, ct, xp, xt);
    ntxent_kernel<<<256, 128, SMEM_BYTES>>>();
    lse_kernel<<<64, 256>>>();
    finish_kernel<<<1, 1>>>(out);
}

// round 12
// speedup vs baseline: 1.1756x; 1.0999x over previous
#include <cuda_runtime.h>
#include <cuda_bf16.h>
#include <math.h>
#include <stdint.h>

#define NROWS 8192
#define DDIM  256
#define TWO_N 16384
// A(64KB) + B0(64KB) + B1(64KB)
#define SMEM_BYTES (3 * 65536)
#define NJOBS 8256   // 64*65 + 64*64 unordered block-pair jobs
#define NCTA  148

// scratch: normalized z rows (bf16), [z1hat; z2hat] = [16384, 256]
__device__ __nv_bfloat16 g_Zn[(size_t)TWO_N * DDIM];
// per-row sum of exp(sim-10), masked diag
__device__ float g_rsum[TWO_N];
// accumulators: 0=price 1=change 2=crit 3=posdot 4=lse_sum
__device__ float g_acc[8];

// ---------------------------------------------------------------------------
__global__ void init_kernel() {
    int i = blockIdx.x * blockDim.x + threadIdx.x;
    if (i < TWO_N) g_rsum[i] = 0.f;
    if (i < 8) g_acc[i] = 0.f;
}

// ---------------------------------------------------------------------------
// Normalize z1/z2 rows (fp32), write bf16 rows to g_Zn, accumulate positive-pair dots.
__global__ void prep_kernel(const float* __restrict__ z1, const float* __restrict__ z2) {
    int warp = (blockIdx.x * blockDim.x + threadIdx.x) >> 5;
    int lane = threadIdx.x & 31;
    if (warp >= NROWS) return;

    const float4* r1 = (const float4*)(z1 + (size_t)warp * DDIM);
    const float4* r2 = (const float4*)(z2 + (size_t)warp * DDIM);
    float4 a0 = r1[lane * 2], a1 = r1[lane * 2 + 1];
    float4 b0 = r2[lane * 2], b1 = r2[lane * 2 + 1];

    float s11 = a0.x*a0.x + a0.y*a0.y + a0.z*a0.z + a0.w*a0.w
              + a1.x*a1.x + a1.y*a1.y + a1.z*a1.z + a1.w*a1.w;
    float s22 = b0.x*b0.x + b0.y*b0.y + b0.z*b0.z + b0.w*b0.w
              + b1.x*b1.x + b1.y*b1.y + b1.z*b1.z + b1.w*b1.w;
    float s12 = a0.x*b0.x + a0.y*b0.y + a0.z*b0.z + a0.w*b0.w
              + a1.x*b1.x + a1.y*b1.y + a1.z*b1.z + a1.w*b1.w;
    #pragma unroll
    for (int o = 16; o; o >>= 1) {
        s11 += __shfl_xor_sync(0xffffffffu, s11, o);
        s22 += __shfl_xor_sync(0xffffffffu, s22, o);
        s12 += __shfl_xor_sync(0xffffffffu, s12, o);
    }
    float n1 = fmaxf(sqrtf(s11), 1e-12f);
    float n2 = fmaxf(sqrtf(s22), 1e-12f);
    float i1 = 1.f / n1, i2 = 1.f / n2;

    __nv_bfloat162* o1 = (__nv_bfloat162*)(g_Zn + (size_t)warp * DDIM + lane * 8);
    __nv_bfloat162* o2 = (__nv_bfloat162*)(g_Zn + (size_t)(warp + NROWS) * DDIM + lane * 8);
    o1[0] = __floats2bfloat162_rn(a0.x * i1, a0.y * i1);
    o1[1] = __floats2bfloat162_rn(a0.z * i1, a0.w * i1);
    o1[2] = __floats2bfloat162_rn(a1.x * i1, a1.y * i1);
    o1[3] = __floats2bfloat162_rn(a1.z * i1, a1.w * i1);
    o2[0] = __floats2bfloat162_rn(b0.x * i2, b0.y * i2);
    o2[1] = __floats2bfloat162_rn(b0.z * i2, b0.w * i2);
    o2[2] = __floats2bfloat162_rn(b1.x * i2, b1.y * i2);
    o2[3] = __floats2bfloat162_rn(b1.z * i2, b1.w * i2);

    if (lane == 0) atomicAdd(&g_acc[3], s12 * i1 * i2);
}

// ---------------------------------------------------------------------------
// Supervised scalar losses: MSE(price) + MSE(change) + BCEWithLogits(crit)
__global__ void sup_kernel(const float* __restrict__ pp, const float* __restrict__ pt,
                           const float* __restrict__ cp, const float* __restrict__ ct,
                           const float* __restrict__ xp, const float* __restrict__ xt) {
    float s0 = 0.f, s1 = 0.f, s2 = 0.f;
    for (int i = blockIdx.x * blockDim.x + threadIdx.x; i < NROWS;
         i += gridDim.x * blockDim.x) {
        float d = pp[i] - pt[i]; s0 = fmaf(d, d, s0);
        d = cp[i] - ct[i];       s1 = fmaf(d, d, s1);
        float x = xp[i], t = xt[i];
        s2 += fmaxf(x, 0.f) - x * t + log1pf(expf(-fabsf(x)));
    }
    #pragma unroll
    for (int o = 16; o; o >>= 1) {
        s0 += __shfl_xor_sync(0xffffffffu, s0, o);
        s1 += __shfl_xor_sync(0xffffffffu, s1, o);
        s2 += __shfl_xor_sync(0xffffffffu, s2, o);
    }
    __shared__ float sh[3][8];
    int lane = threadIdx.x & 31, w = threadIdx.x >> 5;
    if (lane == 0) { sh[0][w] = s0; sh[1][w] = s1; sh[2][w] = s2; }
    __syncthreads();
    if (threadIdx.x == 0) {
        float t0 = 0.f, t1 = 0.f, t2 = 0.f;
        for (int k = 0; k < 8; k++) { t0 += sh[0][k]; t1 += sh[1][k]; t2 += sh[2][k]; }
        atomicAdd(&g_acc[0], t0);
        atomicAdd(&g_acc[1], t1);
        atomicAdd(&g_acc[2], t2);
    }
}

// ---------------------------------------------------------------------------
// GEMM + exp + symmetric row/col accumulation.
__device__ __forceinline__ uint32_t sw_off(int r, int ch) {
    return (uint32_t)(r * 512 + ((ch ^ (r & 7)) << 4));
}

__device__ __forceinline__ void ldsm4(uint32_t* r, uint32_t addr) {
    asm("ldmatrix.sync.aligned.m8n8.x4.shared.b16 {%0,%1,%2,%3}, [%4];"
        : "=r"(r[0]), "=r"(r[1]), "=r"(r[2]), "=r"(r[3]) : "r"(addr) : "memory");
}

__device__ __forceinline__ void mma16816(float* c, const uint32_t* a, const uint32_t* b) {
    asm("mma.sync.aligned.m16n8k16.row.col.f32.bf16.bf16.f32 "
        "{%0,%1,%2,%3}, {%4,%5,%6,%7}, {%8,%9}, {%0,%1,%2,%3};"
        : "+f"(c[0]), "+f"(c[1]), "+f"(c[2]), "+f"(c[3])
        : "r"(a[0]), "r"(a[1]), "r"(a[2]), "r"(a[3]), "r"(b[0]), "r"(b[1]));
}

__device__ __forceinline__ void cp16(uint32_t dst, const void* src) {
    asm volatile("cp.async.cg.shared.global [%0], [%1], 16;"
                 :: "r"(dst), "l"(src));
}
__device__ __forceinline__ void cp_commit() {
    asm volatile("cp.async.commit_group;");
}
template <int N>
__device__ __forceinline__ void cp_wait() {
    asm volatile("cp.async.wait_group %0;" :: "n"(N) : "memory");
}

// exp(10*v - 10) = exp2(v*K - K), K = 10*log2(e); single MUFU EX2
__device__ __forceinline__ float ex2(float x) {
    float r;
    asm("ex2.approx.f32 %0, %1;" : "=f"(r) : "f"(x));
    return r;
}
#define EXPK 14.4269504088896f

// decode flat job m -> (I, d): rows I<64 have 65 jobs (d=0..64), I>=64 have 64.
__device__ __forceinline__ void job_decode(int m, int& I, int& d) {
    if (m < 4160) { I = m / 65; d = m - I * 65; }
    else          { int mm = m - 4160; I = 64 + (mm >> 6); d = mm & 63; }
}

// Persistent-style balanced kernel: 148 CTAs stripe the 8256 (I,J) tile jobs.
// Jobs are I-ordered, so each CTA reloads A at most once.
__global__ void __launch_bounds__(256, 1) ntxent_kernel() {
    extern __shared__ char smem[];
    const int tid  = threadIdx.x;
    const int lane = tid & 31;
    const int wid  = tid >> 5;
    const int warpM = wid >> 1;  // 0..3 (rows)
    const int warpN = wid & 1;   // 0..1 (cols)
    const int g = lane >> 2, q = lane & 3;

    const uint4* gz = (const uint4*)g_Zn;  // 32 uint4 per 256-bf16 row

    uint32_t sbase = (uint32_t)__cvta_generic_to_shared(smem);
    const uint32_t sA = sbase;
    const uint32_t sB[2] = {sbase + 65536, sbase + 2 * 65536};

    const int c = blockIdx.x;
    const int start = (c * NJOBS) / NCTA;
    const int end   = ((c + 1) * NJOBS) / NCTA;

    const int ar_base = warpM * 32 + (lane & 15);
    const int a_chadd = lane >> 4;
    const int bn_thr  = warpN * 64 + ((lane >> 4) << 3) + (lane & 7);
    const int b_chadd = (lane >> 3) & 1;

    float racc[4] = {0.f, 0.f, 0.f, 0.f};
    int curI = -1;
    int buf = 0;

    for (int m = start; m < end; m++) {
        int I, d;
        job_decode(m, I, d);
        const int J = (I + d) & 127;

        if (I != curI) {
            if (curI >= 0) {  // flush row sums of finished row-block
                #pragma unroll
                for (int k = 0; k < 4; k++) {
                    float v = racc[k];
                    v += __shfl_xor_sync(0xffffffffu, v, 1);
                    v += __shfl_xor_sync(0xffffffffu, v, 2);
                    if (q == 0)
                        atomicAdd(&g_rsum[curI * 128 + warpM * 32 +
                                          (k >> 1) * 16 + (k & 1) * 8 + g], v);
                    racc[k] = 0.f;
                }
            }
            // cold load A(I) + B[buf](J). Previous iteration ended with
            // __syncthreads and cp_wait<0>, so both buffers are quiescent.
            #pragma unroll
            for (int it = 0; it < 16; it++) {
                int idx = tid + it * 256;
                int r = idx >> 5, ch = idx & 31;
                uint32_t off = sw_off(r, ch);
                cp16(sA + off, gz + (size_t)(I * 128 + r) * 32 + ch);
                cp16(sB[buf] + off, gz + (size_t)(J * 128 + r) * 32 + ch);
            }
            cp_commit();
            curI = I;
        }

        // prefetch next job's B tile if it shares this A
        int I2 = -1, J2 = -1;
        if (m + 1 < end) {
            int dx;
            job_decode(m + 1, I2, dx);
            J2 = (I2 + dx) & 127;
        }
        const bool pf = (I2 == curI);
        if (pf) {
            const int nb = buf ^ 1;
            #pragma unroll
            for (int it = 0; it < 16; it++) {
                int idx = tid + it * 256;
                int r = idx >> 5, ch = idx & 31;
                cp16(sB[nb] + sw_off(r, ch),
                     gz + (size_t)(J2 * 128 + r) * 32 + ch);
            }
            cp_commit();
            cp_wait<1>();   // current job's tiles landed; prefetch in flight
        } else {
            cp_wait<0>();
        }
        __syncthreads();

        float cc[2][8][4];
        #pragma unroll
        for (int mt = 0; mt < 2; mt++)
            #pragma unroll
            for (int nt = 0; nt < 8; nt++)
                #pragma unroll
                for (int e = 0; e < 4; e++) cc[mt][nt][e] = 0.f;

        #pragma unroll
        for (int ks = 0; ks < 16; ks++) {
            uint32_t a[2][4];
            #pragma unroll
            for (int mt = 0; mt < 2; mt++) {
                int r  = ar_base + mt * 16;
                int ch = ks * 2 + a_chadd;
                ldsm4(a[mt], sA + sw_off(r, ch));
            }
            uint32_t b[8][2];
            #pragma unroll
            for (int p = 0; p < 4; p++) {
                int n  = bn_thr + p * 16;
                int ch = ks * 2 + b_chadd;
                uint32_t t[4];
                ldsm4(t, sB[buf] + sw_off(n, ch));
                b[2 * p][0] = t[0]; b[2 * p][1] = t[1];
                b[2 * p + 1][0] = t[2]; b[2 * p + 1][1] = t[3];
            }
            #pragma unroll
            for (int mt = 0; mt < 2; mt++)
                #pragma unroll
                for (int nt = 0; nt < 8; nt++)
                    mma16816(cc[mt][nt], a[mt], b[nt]);
        }

        // epilogue: exp(10*sim - 10); row-side into racc, col-side (transpose,
        // feeds row sums of block J) via shfl-reduce + global float atomics.
        const bool diag = (d == 0);
        #pragma unroll
        for (int nt = 0; nt < 8; nt++) {
            float cs0 = 0.f, cs1 = 0.f;
            #pragma unroll
            for (int mt = 0; mt < 2; mt++) {
                #pragma unroll
                for (int h = 0; h < 2; h++) {
                    float e0 = ex2(fmaf(cc[mt][nt][h * 2 + 0], EXPK, -EXPK));
                    float e1 = ex2(fmaf(cc[mt][nt][h * 2 + 1], EXPK, -EXPK));
                    if (diag) {
                        int rl = warpM * 32 + mt * 16 + h * 8 + g;
                        int cb = warpN * 64 + nt * 8 + 2 * q;
                        if (rl == cb)     e0 = 0.f;
                        if (rl == cb + 1) e1 = 0.f;
                    }
                    racc[mt * 2 + h] += e0 + e1;
                    cs0 += e0; cs1 += e1;
                }
            }
            if (!diag) {
                #pragma unroll
                for (int o = 4; o <= 16; o <<= 1) {
                    cs0 += __shfl_xor_sync(0xffffffffu, cs0, o);
                    cs1 += __shfl_xor_sync(0xffffffffu, cs1, o);
                }
                if (lane < 4) {
                    int col = warpN * 64 + nt * 8 + 2 * lane;
                    atomicAdd(&g_rsum[J * 128 + col],     cs0);
                    atomicAdd(&g_rsum[J * 128 + col + 1], cs1);
                }
            }
        }
        __syncthreads();  // all reads of sB[buf]/sA done before next overwrite
        if (pf) buf ^= 1;
    }

    // final flush of the last row-block's sums
    #pragma unroll
    for (int k = 0; k < 4; k++) {
        float v = racc[k];
        v += __shfl_xor_sync(0xffffffffu, v, 1);
        v += __shfl_xor_sync(0xffffffffu, v, 2);
        if (q == 0)
            atomicAdd(&g_rsum[curI * 128 + warpM * 32 +
                              (k >> 1) * 16 + (k & 1) * 8 + g], v);
    }
}

// ---------------------------------------------------------------------------
__global__ void lse_kernel() {
    int i = blockIdx.x * blockDim.x + threadIdx.x;
    float lse = 10.f + __logf(g_rsum[i]);
    #pragma unroll
    for (int o = 16; o; o >>= 1) lse += __shfl_xor_sync(0xffffffffu, lse, o);
    __shared__ float sh[8];
    int lane = threadIdx.x & 31, w = threadIdx.x >> 5;
    if (lane == 0) sh[w] = lse;
    __syncthreads();
    if (threadIdx.x == 0) {
        float t = 0.f;
        for (int k = 0; k < 8; k++) t += sh[k];
        atomicAdd(&g_acc[4], t);
    }
}

// ---------------------------------------------------------------------------
__global__ void finish_kernel(float* out) {
    const float inv = 1.f / 8192.f;
    float sup = g_acc[0] * inv + 0.5f * g_acc[1] * inv + 0.3f * g_acc[2] * inv;
    // sum_i sim_pos = 2 * posdotsum / 0.1 = 20 * posdotsum
    float ssl = (g_acc[4] - 20.f * g_acc[3]) * (1.f / 16384.f);
    out[0] = sup + 0.1f * ssl;
}

// ---------------------------------------------------------------------------
extern "C" void kernel_launch(void* const* d_in, const int* in_sizes, int n_in,
                              void* d_out, int out_size) {
    const float* pp = (const float*)d_in[0];
    const float* pt = (const float*)d_in[1];
    const float* cp = (const float*)d_in[2];
    const float* ct = (const float*)d_in[3];
    const float* xp = (const float*)d_in[4];
    const float* xt = (const float*)d_in[5];
    const float* z1 = (const float*)d_in[6];
    const float* z2 = (const float*)d_in[7];
    float* out = (float*)d_out;

    cudaFuncSetAttribute(ntxent_kernel, cudaFuncAttributeMaxDynamicSharedMemorySize,
                         SMEM_BYTES);

    init_kernel<<<64, 256>>>();
    prep_kernel<<<NROWS / 8, 256>>>(z1, z2);
    sup_kernel<<<32, 256>>>(pp, pt, cp, ct, xp, xt);
    ntxent_kernel<<<NCTA, 256, SMEM_BYTES>>>();
    lse_kernel<<<64, 256>>>();
    finish_kernel<<<1, 1>>>(out);
}

// round 14
// speedup vs baseline: 1.1858x; 1.0087x over previous
#include <cuda_runtime.h>
#include <cuda_bf16.h>
#include <math.h>
#include <stdint.h>

#define NROWS 8192
#define DDIM  256
#define TWO_N 16384
// A(64KB) + B0(64KB) + B1(64KB)
#define SMEM_BYTES (3 * 65536)

// scratch: normalized z rows (bf16), [z1hat; z2hat] = [16384, 256]
__device__ __nv_bfloat16 g_Zn[(size_t)TWO_N * DDIM];
// per-row sum of exp(sim-10), masked diag
__device__ float g_rsum[TWO_N];
// accumulators: 0=price 1=change 2=crit 3=posdot 4=lse_sum
__device__ float g_acc[8];
__device__ int g_done;

// ---------------------------------------------------------------------------
__global__ void init_kernel() {
    int i = blockIdx.x * blockDim.x + threadIdx.x;
    if (i < TWO_N) g_rsum[i] = 0.f;
    if (i < 8) g_acc[i] = 0.f;
    if (i == 8) g_done = 0;
}

// ---------------------------------------------------------------------------
// Fused: normalize z1/z2 rows -> bf16 g_Zn + positive-pair dots (all blocks),
// plus supervised losses (blocks 0..31).
__global__ void prep_kernel(const float* __restrict__ z1, const float* __restrict__ z2,
                            const float* __restrict__ pp, const float* __restrict__ pt,
                            const float* __restrict__ cp, const float* __restrict__ ct,
                            const float* __restrict__ xp, const float* __restrict__ xt) {
    // ---- supervised part: blocks 0..31 cover 8192 elements exactly once
    if (blockIdx.x < 32) {
        int i = blockIdx.x * blockDim.x + threadIdx.x;
        float d = pp[i] - pt[i]; float s0 = d * d;
        d = cp[i] - ct[i];       float s1 = d * d;
        float x = xp[i], t = xt[i];
        float s2 = fmaxf(x, 0.f) - x * t + log1pf(expf(-fabsf(x)));
        #pragma unroll
        for (int o = 16; o; o >>= 1) {
            s0 += __shfl_xor_sync(0xffffffffu, s0, o);
            s1 += __shfl_xor_sync(0xffffffffu, s1, o);
            s2 += __shfl_xor_sync(0xffffffffu, s2, o);
        }
        if ((threadIdx.x & 31) == 0) {
            atomicAdd(&g_acc[0], s0);
            atomicAdd(&g_acc[1], s1);
            atomicAdd(&g_acc[2], s2);
        }
    }

    // ---- normalization part: one warp per row
    int warp = (blockIdx.x * blockDim.x + threadIdx.x) >> 5;
    int lane = threadIdx.x & 31;
    if (warp >= NROWS) return;

    const float4* r1 = (const float4*)(z1 + (size_t)warp * DDIM);
    const float4* r2 = (const float4*)(z2 + (size_t)warp * DDIM);
    float4 a0 = r1[lane * 2], a1 = r1[lane * 2 + 1];
    float4 b0 = r2[lane * 2], b1 = r2[lane * 2 + 1];

    float s11 = a0.x*a0.x + a0.y*a0.y + a0.z*a0.z + a0.w*a0.w
              + a1.x*a1.x + a1.y*a1.y + a1.z*a1.z + a1.w*a1.w;
    float s22 = b0.x*b0.x + b0.y*b0.y + b0.z*b0.z + b0.w*b0.w
              + b1.x*b1.x + b1.y*b1.y + b1.z*b1.z + b1.w*b1.w;
    float s12 = a0.x*b0.x + a0.y*b0.y + a0.z*b0.z + a0.w*b0.w
              + a1.x*b1.x + a1.y*b1.y + a1.z*b1.z + a1.w*b1.w;
    #pragma unroll
    for (int o = 16; o; o >>= 1) {
        s11 += __shfl_xor_sync(0xffffffffu, s11, o);
        s22 += __shfl_xor_sync(0xffffffffu, s22, o);
        s12 += __shfl_xor_sync(0xffffffffu, s12, o);
    }
    float n1 = fmaxf(sqrtf(s11), 1e-12f);
    float n2 = fmaxf(sqrtf(s22), 1e-12f);
    float i1 = 1.f / n1, i2 = 1.f / n2;

    __nv_bfloat162* o1 = (__nv_bfloat162*)(g_Zn + (size_t)warp * DDIM + lane * 8);
    __nv_bfloat162* o2 = (__nv_bfloat162*)(g_Zn + (size_t)(warp + NROWS) * DDIM + lane * 8);
    o1[0] = __floats2bfloat162_rn(a0.x * i1, a0.y * i1);
    o1[1] = __floats2bfloat162_rn(a0.z * i1, a0.w * i1);
    o1[2] = __floats2bfloat162_rn(a1.x * i1, a1.y * i1);
    o1[3] = __floats2bfloat162_rn(a1.z * i1, a1.w * i1);
    o2[0] = __floats2bfloat162_rn(b0.x * i2, b0.y * i2);
    o2[1] = __floats2bfloat162_rn(b0.z * i2, b0.w * i2);
    o2[2] = __floats2bfloat162_rn(b1.x * i2, b1.y * i2);
    o2[3] = __floats2bfloat162_rn(b1.z * i2, b1.w * i2);

    if (lane == 0) atomicAdd(&g_acc[3], s12 * i1 * i2);
}

// ---------------------------------------------------------------------------
// GEMM + exp + symmetric row/col accumulation.
__device__ __forceinline__ uint32_t sw_off(int r, int ch) {
    return (uint32_t)(r * 512 + ((ch ^ (r & 7)) << 4));
}

__device__ __forceinline__ void ldsm4(uint32_t* r, uint32_t addr) {
    asm("ldmatrix.sync.aligned.m8n8.x4.shared.b16 {%0,%1,%2,%3}, [%4];"
        : "=r"(r[0]), "=r"(r[1]), "=r"(r[2]), "=r"(r[3]) : "r"(addr) : "memory");
}

__device__ __forceinline__ void mma16816(float* c, const uint32_t* a, const uint32_t* b) {
    asm("mma.sync.aligned.m16n8k16.row.col.f32.bf16.bf16.f32 "
        "{%0,%1,%2,%3}, {%4,%5,%6,%7}, {%8,%9}, {%0,%1,%2,%3};"
        : "+f"(c[0]), "+f"(c[1]), "+f"(c[2]), "+f"(c[3])
        : "r"(a[0]), "r"(a[1]), "r"(a[2]), "r"(a[3]), "r"(b[0]), "r"(b[1]));
}

__device__ __forceinline__ void cp16(uint32_t dst, const void* src) {
    asm volatile("cp.async.cg.shared.global [%0], [%1], 16;"
                 :: "r"(dst), "l"(src));
}
__device__ __forceinline__ void cp_commit() {
    asm volatile("cp.async.commit_group;");
}
template <int N>
__device__ __forceinline__ void cp_wait() {
    asm volatile("cp.async.wait_group %0;" :: "n"(N) : "memory");
}

// exp(10*v - 10) = exp2(v*K - K), K = 10*log2(e); single MUFU EX2
__device__ __forceinline__ float ex2(float x) {
    float r;
    asm("ex2.approx.f32 %0, %1;" : "=f"(r) : "f"(x));
    return r;
}
#define EXPK 14.4269504088896f

__global__ void __launch_bounds__(256, 1) ntxent_kernel() {
    extern __shared__ char smem[];
    const int tid  = threadIdx.x;
    const int lane = tid & 31;
    const int wid  = tid >> 5;
    const int warpM = wid >> 1;  // 0..3 (rows)
    const int warpN = wid & 1;   // 0..1 (cols)
    const int br = blockIdx.x;   // 0..127 row block
    // wrap mapping: CTA br computes tiles j = br..br+63 (mod 128),
    // plus antipodal j=br+64 when br<64. Each unordered pair once.
    const int ntiles = (br < 64) ? 65 : 64;

    const uint4* gz = (const uint4*)g_Zn;  // 32 uint4 per 256-bf16 row

    uint32_t sbase = (uint32_t)__cvta_generic_to_shared(smem);
    const uint32_t sA = sbase;
    const uint32_t sB[2] = {sbase + 65536, sbase + 2 * 65536};

    // prologue: A tile (rows br*128..) + B tile jj=0 (j=br, the diag tile)
    #pragma unroll
    for (int it = 0; it < 16; it++) {
        int idx = tid + it * 256;
        int r = idx >> 5, ch = idx & 31;
        uint32_t off = sw_off(r, ch);
        cp16(sA + off, gz + (size_t)(br * 128 + r) * 32 + ch);
        cp16(sB[0] + off, gz + (size_t)(br * 128 + r) * 32 + ch);
    }
    cp_commit();

    const int g = lane >> 2, q = lane & 3;
    float racc[4] = {0.f, 0.f, 0.f, 0.f};

    const int ar_base = warpM * 32 + (lane & 15);
    const int a_chadd = lane >> 4;
    const int bn_thr  = warpN * 64 + ((lane >> 4) << 3) + (lane & 7);
    const int b_chadd = (lane >> 3) & 1;

    for (int jj = 0; jj < ntiles; jj++) {
        const int j = (br + jj) & 127;
        const int cur = jj & 1;

        cp_wait<0>();      // drain the single pending group (tile jj's data)
        __syncthreads();   // all warps: tile jj visible AND tile jj-1 consumed

        // prefetch tile jj+1 into the other buffer (safe: post-barrier, the
        // buffer's last readers finished tile jj-1 before arriving here)
        if (jj + 1 < ntiles) {
            const int nxt = cur ^ 1;
            const int j2 = (br + jj + 1) & 127;
            #pragma unroll
            for (int it = 0; it < 16; it++) {
                int idx = tid + it * 256;
                int r = idx >> 5, ch = idx & 31;
                cp16(sB[nxt] + sw_off(r, ch),
                     gz + (size_t)(j2 * 128 + r) * 32 + ch);
            }
            cp_commit();
        }

        float c[2][8][4];
        #pragma unroll
        for (int mt = 0; mt < 2; mt++)
            #pragma unroll
            for (int nt = 0; nt < 8; nt++)
                #pragma unroll
                for (int e = 0; e < 4; e++) c[mt][nt][e] = 0.f;

        #pragma unroll
        for (int ks = 0; ks < 16; ks++) {
            uint32_t a[2][4];
            #pragma unroll
            for (int mt = 0; mt < 2; mt++) {
                int r  = ar_base + mt * 16;
                int ch = ks * 2 + a_chadd;
                ldsm4(a[mt], sA + sw_off(r, ch));
            }
            uint32_t b[8][2];
            #pragma unroll
            for (int p = 0; p < 4; p++) {
                int n  = bn_thr + p * 16;
                int ch = ks * 2 + b_chadd;
                uint32_t t[4];
                ldsm4(t, sB[cur] + sw_off(n, ch));
                b[2 * p][0] = t[0]; b[2 * p][1] = t[1];
                b[2 * p + 1][0] = t[2]; b[2 * p + 1][1] = t[3];
            }
            #pragma unroll
            for (int mt = 0; mt < 2; mt++)
                #pragma unroll
                for (int nt = 0; nt < 8; nt++)
                    mma16816(c[mt][nt], a[mt], b[nt]);
        }

        // epilogue: exp(10*sim - 10); row-side into racc, col-side (transpose,
        // feeds row sums of block j) via shfl-reduce + global float atomics.
        const bool diag = (jj == 0);
        #pragma unroll
        for (int nt = 0; nt < 8; nt++) {
            float cs0 = 0.f, cs1 = 0.f;
            #pragma unroll
            for (int mt = 0; mt < 2; mt++) {
                #pragma unroll
                for (int h = 0; h < 2; h++) {
                    float e0 = ex2(fmaf(c[mt][nt][h * 2 + 0], EXPK, -EXPK));
                    float e1 = ex2(fmaf(c[mt][nt][h * 2 + 1], EXPK, -EXPK));
                    if (diag) {
                        int rl = warpM * 32 + mt * 16 + h * 8 + g;
                        int cb = warpN * 64 + nt * 8 + 2 * q;
                        if (rl == cb)     e0 = 0.f;
                        if (rl == cb + 1) e1 = 0.f;
                    }
                    racc[mt * 2 + h] += e0 + e1;
                    cs0 += e0; cs1 += e1;
                }
            }
            if (!diag) {
                #pragma unroll
                for (int o = 4; o <= 16; o <<= 1) {
                    cs0 += __shfl_xor_sync(0xffffffffu, cs0, o);
                    cs1 += __shfl_xor_sync(0xffffffffu, cs1, o);
                }
                if (lane < 4) {
                    int col = warpN * 64 + nt * 8 + 2 * lane;
                    atomicAdd(&g_rsum[j * 128 + col],     cs0);
                    atomicAdd(&g_rsum[j * 128 + col + 1], cs1);
                }
            }
        }
    }

    // row-side: reduce racc across quad lanes, one atomic per row per warp
    #pragma unroll
    for (int k = 0; k < 4; k++) {
        float v = racc[k];
        v += __shfl_xor_sync(0xffffffffu, v, 1);
        v += __shfl_xor_sync(0xffffffffu, v, 2);
        if (q == 0) {
            int r = warpM * 32 + (k >> 1) * 16 + (k & 1) * 8 + g;
            atomicAdd(&g_rsum[br * 128 + r], v);
        }
    }
}

// ---------------------------------------------------------------------------
// Fused lse + finish: 64 blocks reduce lse; the last block writes the output.
__global__ void lse_kernel(float* __restrict__ out) {
    int i = blockIdx.x * blockDim.x + threadIdx.x;
    float lse = 10.f + __logf(g_rsum[i]);
    #pragma unroll
    for (int o = 16; o; o >>= 1) lse += __shfl_xor_sync(0xffffffffu, lse, o);
    __shared__ float sh[8];
    __shared__ bool last;
    int lane = threadIdx.x & 31, w = threadIdx.x >> 5;
    if (lane == 0) sh[w] = lse;
    __syncthreads();
    if (threadIdx.x == 0) {
        float t = 0.f;
        for (int k = 0; k < 8; k++) t += sh[k];
        atomicAdd(&g_acc[4], t);
        __threadfence();
        last = (atomicAdd(&g_done, 1) == 63);
    }
    __syncthreads();
    if (last && threadIdx.x == 0) {
        const float inv = 1.f / 8192.f;
        float sup = g_acc[0] * inv + 0.5f * g_acc[1] * inv + 0.3f * g_acc[2] * inv;
        // sum_i sim_pos = 2 * posdotsum / 0.1 = 20 * posdotsum
        float ssl = (g_acc[4] - 20.f * g_acc[3]) * (1.f / 16384.f);
        out[0] = sup + 0.1f * ssl;
    }
}

// ---------------------------------------------------------------------------
extern "C" void kernel_launch(void* const* d_in, const int* in_sizes, int n_in,
                              void* d_out, int out_size) {
    const float* pp = (const float*)d_in[0];
    const float* pt = (const float*)d_in[1];
    const float* cp = (const float*)d_in[2];
    const float* ct = (const float*)d_in[3];
    const float* xp = (const float*)d_in[4];
    const float* xt = (const float*)d_in[5];
    const float* z1 = (const float*)d_in[6];
    const float* z2 = (const float*)d_in[7];
    float* out = (float*)d_out;

    cudaFuncSetAttribute(ntxent_kernel, cudaFuncAttributeMaxDynamicSharedMemorySize,
                         SMEM_BYTES);

    init_kernel<<<64, 256>>>();
    prep_kernel<<<NROWS / 8, 256>>>(z1, z2, pp, pt, cp, ct, xp, xt);
    ntxent_kernel<<<128, 256, SMEM_BYTES>>>();
    lse_kernel<<<64, 256>>>(out);
}